// round 6
// baseline (speedup 1.0000x reference)
#include <cuda_runtime.h>

#define NROWS 65536
#define ZD    256
#define KCODES 1024
#define BM 128
#define BN 128
#define BK 8
#define LDB  132             // Bs row stride (floats)
#define LDA2 264             // As2 (duplicated-pair) row stride (floats)
#define NBLK (NROWS / BM)    // 512

#define ZQ_ELEMS ((size_t)NROWS * ZD)
#define IDX_OFF  ZQ_ELEMS
#define LOSS_OFF (ZQ_ELEMS + (size_t)NROWS)

typedef unsigned long long ull;

__device__ float g_enorm[KCODES];
__device__ float g_znorm[NROWS];
__device__ float g_partial[NBLK];

// ---- packed fp32x2 helpers (sm_100+); each half rounds exactly like scalar FFMA ----
__device__ __forceinline__ ull pack2(float lo, float hi) {
    ull r; asm("mov.b64 %0, {%1, %2};" : "=l"(r) : "f"(lo), "f"(hi)); return r;
}
__device__ __forceinline__ void unpack2(float& lo, float& hi, ull v) {
    asm("mov.b64 {%0, %1}, %2;" : "=f"(lo), "=f"(hi) : "l"(v));
}
__device__ __forceinline__ ull ffma2(ull a, ull b, ull c) {
    ull d; asm("fma.rn.f32x2 %0, %1, %2, %3;" : "=l"(d) : "l"(a), "l"(b), "l"(c)); return d;
}

// ================= K1: sum-of-squares per row, XLA row-reduce-tree bit-exact ==========
// (destination selected in device code; device symbols must never be host kernel args)
__global__ void sqsum_tree_kernel(const float* __restrict__ src, int nrows, int mode)
{
    int row = blockIdx.x * 8 + (threadIdx.x >> 5);
    if (row >= nrows) return;
    int lane = threadIdx.x & 31;
    const float2* p = (const float2*)(src + (size_t)row * ZD);

    float acc[4];
#pragma unroll
    for (int j = 0; j < 4; j++) {
        float2 v = p[lane + 32 * j];
        float a = __fmul_rn(v.x, v.x);
        float b = __fmul_rn(v.y, v.y);
        acc[j] = __fadd_rn(a, b);
    }
#pragma unroll
    for (int off = 16; off; off >>= 1) {
#pragma unroll
        for (int j = 0; j < 4; j++)
            acc[j] = __fadd_rn(acc[j], __shfl_down_sync(0xffffffffu, acc[j], off));
    }
    if (lane == 0) {
        float l = __fadd_rn(acc[0], acc[2]);
        float r = __fadd_rn(acc[1], acc[3]);
        float s = __fadd_rn(l, r);
        if (mode == 0) g_znorm[row] = s;
        else           g_enorm[row] = s;
    }
}

// ================= K2: fused GEMM + quantized-score argmin + gather + loss =============
// v2: code-paired f32x2 accumulators (b = genuine LDS pair, a = smem-duplicated pair;
// zero per-kk pack MOVs), double-buffered smem, single barrier per k-chunk, prefetched
// LDG. Per-(row,code) fp32 accumulation order identical to the round-5 passing kernel.
__global__ __launch_bounds__(256, 2) void vq_main(
    const float* __restrict__ Z, const float* __restrict__ E, float* __restrict__ out)
{
    __shared__ __align__(16) float sA[2][BK * LDA2];   // duplicated-pair A tiles
    __shared__ __align__(16) float sB[2][BK * LDB];    // B tiles
    __shared__ float sZn[BM];
    __shared__ float sBestV[BM];
    __shared__ int   sBestI[BM];
    __shared__ float sRed[8];

    const int tid = threadIdx.x;
    const int tx = tid & 15;       // code micro-tile coordinate (8 codes)
    const int ty = tid >> 4;       // row micro-tile coordinate (8 rows)
    const int row0 = blockIdx.x * BM;

    if (tid < BM) {
        sBestV[tid] = 3.402823466e38f;
        sBestI[tid] = 0;
        sZn[tid] = g_znorm[row0 + tid];
    }
    // ordered before any read by the first __syncthreads in the mainloop

    const float* Ablk = Z + (size_t)row0 * ZD;

    // loader mapping: each thread owns 4 consecutive k of one row/code per chunk
    const int lm = tid >> 1;            // row (for A) / code (for B), 0..127
    const int lc = (tid & 1) * 4;       // k offset within chunk, 0 or 4

    for (int ct = 0; ct < KCODES; ct += BN) {
        ull acc[8][4];   // [row r][code-pair p]; lanes = codes (2p, 2p+1)
#pragma unroll
        for (int r = 0; r < 8; r++)
#pragma unroll
            for (int p = 0; p < 4; p++) acc[r][p] = 0ull;

        const float* Bblk = E + (size_t)ct * ZD;

        // ---- preload + store chunk 0 into buffer 0 ----
        {
            float4 pa = *(const float4*)(Ablk + (size_t)lm * ZD + lc);
            float4 pb = *(const float4*)(Bblk + (size_t)lm * ZD + lc);
            float* a0 = &sA[0][0];
            float* b0 = &sB[0][0];
            ((ull*)(a0 + (lc + 0) * LDA2))[lm] = pack2(pa.x, pa.x);
            ((ull*)(a0 + (lc + 1) * LDA2))[lm] = pack2(pa.y, pa.y);
            ((ull*)(a0 + (lc + 2) * LDA2))[lm] = pack2(pa.z, pa.z);
            ((ull*)(a0 + (lc + 3) * LDA2))[lm] = pack2(pa.w, pa.w);
            b0[(lc + 0) * LDB + lm] = pb.x;
            b0[(lc + 1) * LDB + lm] = pb.y;
            b0[(lc + 2) * LDB + lm] = pb.z;
            b0[(lc + 3) * LDB + lm] = pb.w;
        }

        int buf = 0;
        for (int k0 = 0; k0 < ZD; k0 += BK) {    // k strictly ascending (serial order)
            const int nxt = k0 + BK;
            float4 qa, qb;
            if (nxt < ZD) {                       // prefetch next chunk before barrier
                qa = *(const float4*)(Ablk + (size_t)lm * ZD + nxt + lc);
                qb = *(const float4*)(Bblk + (size_t)lm * ZD + nxt + lc);
            }
            __syncthreads();                      // chunk k0 stores visible; buf^1 free
            if (nxt < ZD) {                       // fill alternate buffer during compute
                float* aw = &sA[buf ^ 1][0];
                float* bw = &sB[buf ^ 1][0];
                ((ull*)(aw + (lc + 0) * LDA2))[lm] = pack2(qa.x, qa.x);
                ((ull*)(aw + (lc + 1) * LDA2))[lm] = pack2(qa.y, qa.y);
                ((ull*)(aw + (lc + 2) * LDA2))[lm] = pack2(qa.z, qa.z);
                ((ull*)(aw + (lc + 3) * LDA2))[lm] = pack2(qa.w, qa.w);
                bw[(lc + 0) * LDB + lm] = qb.x;
                bw[(lc + 1) * LDB + lm] = qb.y;
                bw[(lc + 2) * LDB + lm] = qb.z;
                bw[(lc + 3) * LDB + lm] = qb.w;
            }
            const float* Abuf = &sA[buf][0];
            const float* Bbuf = &sB[buf][0];
#pragma unroll
            for (int kk = 0; kk < BK; kk++) {
                const ulonglong2* ar = (const ulonglong2*)(Abuf + kk * LDA2 + ty * 16);
                ulonglong2 u0 = ar[0], u1 = ar[1], u2 = ar[2], u3 = ar[3];
                ull aa[8] = { u0.x, u0.y, u1.x, u1.y, u2.x, u2.y, u3.x, u3.y };
                const ulonglong2* br = (const ulonglong2*)(Bbuf + kk * LDB + tx * 8);
                ulonglong2 w0 = br[0], w1 = br[1];
                ull bb[4] = { w0.x, w0.y, w1.x, w1.y };
#pragma unroll
                for (int p = 0; p < 4; p++)
#pragma unroll
                    for (int r = 0; r < 8; r++)
                        acc[r][p] = ffma2(aa[r], bb[p], acc[r][p]);
            }
            buf ^= 1;
        }

        // ---- reference-exact scores: s = fl(fl(zn+en) - 2*dot); argmin, first-index ----
        float v[8]; int vi[8];
#pragma unroll
        for (int r = 0; r < 8; r++) { v[r] = 3.402823466e38f; vi[r] = 0; }
#pragma unroll
        for (int p = 0; p < 4; p++) {              // codes ascend: 2p, 2p+1
            int c0 = ct + tx * 8 + 2 * p;
            float en0 = g_enorm[c0];
            float en1 = g_enorm[c0 + 1];
#pragma unroll
            for (int r = 0; r < 8; r++) {
                float lo, hi; unpack2(lo, hi, acc[r][p]);
                float zn = sZn[ty * 8 + r];
                float s0 = __fmaf_rn(-2.0f, lo, __fadd_rn(zn, en0)); // 2*dot exact
                float s1 = __fmaf_rn(-2.0f, hi, __fadd_rn(zn, en1));
                if (s0 < v[r]) { v[r] = s0; vi[r] = c0; }
                if (s1 < v[r]) { v[r] = s1; vi[r] = c0 + 1; }
            }
        }
#pragma unroll
        for (int r = 0; r < 8; r++) {
            float mv = v[r]; int mi = vi[r];
#pragma unroll
            for (int o = 8; o; o >>= 1) {
                float ov = __shfl_xor_sync(0xffffffffu, mv, o);
                int   oi = __shfl_xor_sync(0xffffffffu, mi, o);
                if (ov < mv || (ov == mv && oi < mi)) { mv = ov; mi = oi; }
            }
            if (tx == 0) {
                int rr = ty * 8 + r;   // unique writer per rr across all ct tiles
                if (mv < sBestV[rr] || (mv == sBestV[rr] && mi < sBestI[rr])) {
                    sBestV[rr] = mv; sBestI[rr] = mi;
                }
            }
        }
    }
    __syncthreads();

    // ---- gather z_q; z_q_st = fl(z + fl(z_q - z)) exactly as reference; loss partial ----
    float lsum = 0.0f;
    for (int e = tid; e < BM * (ZD / 4); e += 256) {
        int m = e >> 6;
        int c4 = (e & 63) * 4;
        int idx = sBestI[m];
        float4 q  = *(const float4*)(E + (size_t)idx * ZD + c4);
        float4 z4 = *(const float4*)(Ablk + (size_t)m * ZD + c4);
        float d0 = __fadd_rn(q.x, -z4.x), d1 = __fadd_rn(q.y, -z4.y);
        float d2 = __fadd_rn(q.z, -z4.z), d3 = __fadd_rn(q.w, -z4.w);
        float4 o;
        o.x = __fadd_rn(z4.x, d0); o.y = __fadd_rn(z4.y, d1);
        o.z = __fadd_rn(z4.z, d2); o.w = __fadd_rn(z4.w, d3);
        lsum += d0 * d0 + d1 * d1 + d2 * d2 + d3 * d3;
        *(float4*)(out + (size_t)(row0 + m) * ZD + c4) = o;
    }
    if (tid < BM) out[IDX_OFF + row0 + tid] = (float)sBestI[tid];

#pragma unroll
    for (int o = 16; o; o >>= 1) lsum += __shfl_xor_sync(0xffffffffu, lsum, o);
    if ((tid & 31) == 0) sRed[tid >> 5] = lsum;
    __syncthreads();
    if (tid < 8) {
        float x = sRed[tid];
        x += __shfl_xor_sync(0xffu, x, 4);
        x += __shfl_xor_sync(0xffu, x, 2);
        x += __shfl_xor_sync(0xffu, x, 1);
        if (tid == 0) g_partial[blockIdx.x] = x;
    }
}

// ================= K3: deterministic final loss reduction =================
__global__ void finalize_kernel(float* __restrict__ out) {
    __shared__ float s[16];
    int t = threadIdx.x;
    float v = g_partial[t];
#pragma unroll
    for (int o = 16; o; o >>= 1) v += __shfl_xor_sync(0xffffffffu, v, o);
    if ((t & 31) == 0) s[t >> 5] = v;
    __syncthreads();
    if (t < 16) {
        float x = s[t];
        x += __shfl_xor_sync(0xffffu, x, 8);
        x += __shfl_xor_sync(0xffffu, x, 4);
        x += __shfl_xor_sync(0xffffu, x, 2);
        x += __shfl_xor_sync(0xffffu, x, 1);
        if (t == 0) {
            float mean = x / (float)((size_t)NROWS * ZD);
            out[LOSS_OFF] = mean + 0.25f * mean;   // (1 + BETA) * mean((z_q - z)^2)
        }
    }
}

extern "C" void kernel_launch(void* const* d_in, const int* in_sizes, int n_in,
                              void* d_out, int out_size) {
    const float* Z = (const float*)d_in[0];
    const float* E = (const float*)d_in[1];
    if (n_in >= 2 && in_sizes[0] < in_sizes[1]) { const float* t = Z; Z = E; E = t; }
    float* out = (float*)d_out;

    sqsum_tree_kernel<<<(NROWS + 7) / 8, 256>>>(Z, NROWS, 0);   // -> g_znorm
    sqsum_tree_kernel<<<(KCODES + 7) / 8, 256>>>(E, KCODES, 1); // -> g_enorm
    vq_main<<<NBLK, 256>>>(Z, E, out);
    finalize_kernel<<<1, 512>>>(out);
}

// round 7
// speedup vs baseline: 1.2937x; 1.2937x over previous
#include <cuda_runtime.h>

#define NROWS 65536
#define ZD    256
#define KCODES 1024
#define BM 128
#define BN 128
#define BK 16
#define LDA 132              // padded smem stride
#define NBLK (NROWS / BM)    // 512

#define ZQ_ELEMS ((size_t)NROWS * ZD)
#define IDX_OFF  ZQ_ELEMS
#define LOSS_OFF (ZQ_ELEMS + (size_t)NROWS)

typedef unsigned long long ull;

__device__ float g_enorm[KCODES];
__device__ float g_znorm[NROWS];
__device__ float g_partial[NBLK];

// ---- packed fp32x2 helpers (sm_100+); each half rounds exactly like scalar FFMA ----
__device__ __forceinline__ ull pack2(float lo, float hi) {
    ull r; asm("mov.b64 %0, {%1, %2};" : "=l"(r) : "f"(lo), "f"(hi)); return r;
}
__device__ __forceinline__ void unpack2(float& lo, float& hi, ull v) {
    asm("mov.b64 {%0, %1}, %2;" : "=f"(lo), "=f"(hi) : "l"(v));
}
__device__ __forceinline__ ull ffma2(ull a, ull b, ull c) {
    ull d; asm("fma.rn.f32x2 %0, %1, %2, %3;" : "=l"(d) : "l"(a), "l"(b), "l"(c)); return d;
}

// ================= K1: sum-of-squares per row, XLA row-reduce-tree bit-exact ==========
// (destination selected in device code; device symbols must never be host kernel args)
__global__ void sqsum_tree_kernel(const float* __restrict__ src, int nrows, int mode)
{
    int row = blockIdx.x * 8 + (threadIdx.x >> 5);
    if (row >= nrows) return;
    int lane = threadIdx.x & 31;
    const float2* p = (const float2*)(src + (size_t)row * ZD);

    float acc[4];
#pragma unroll
    for (int j = 0; j < 4; j++) {
        float2 v = p[lane + 32 * j];
        float a = __fmul_rn(v.x, v.x);
        float b = __fmul_rn(v.y, v.y);
        acc[j] = __fadd_rn(a, b);
    }
#pragma unroll
    for (int off = 16; off; off >>= 1) {
#pragma unroll
        for (int j = 0; j < 4; j++)
            acc[j] = __fadd_rn(acc[j], __shfl_down_sync(0xffffffffu, acc[j], off));
    }
    if (lane == 0) {
        float l = __fadd_rn(acc[0], acc[2]);
        float r = __fadd_rn(acc[1], acc[3]);
        float s = __fadd_rn(l, r);
        if (mode == 0) g_znorm[row] = s;
        else           g_enorm[row] = s;
    }
}

// ================= K2: fused GEMM + quantized-score argmin + gather + loss =============
// v3 = round-5 inner loop (row-paired f32x2 acc, b broadcast duplicated in REGISTERS —
// smem reads stay at the balanced 64B/thread/kk crossbar floor) + double-buffered smem
// with ONE barrier per k-chunk and LDG prefetch issued before the barrier.
__global__ __launch_bounds__(256, 2) void vq_main(
    const float* __restrict__ Z, const float* __restrict__ E, float* __restrict__ out)
{
    __shared__ __align__(16) float sA[2][BK * LDA];
    __shared__ __align__(16) float sB[2][BK * LDA];
    __shared__ float sZn[BM];
    __shared__ float sBestV[BM];
    __shared__ int   sBestI[BM];
    __shared__ float sRed[8];

    const int tid = threadIdx.x;
    const int tx = tid & 15;       // code micro-tile coordinate
    const int ty = tid >> 4;       // row micro-tile coordinate
    const int row0 = blockIdx.x * BM;

    if (tid < BM) {
        sBestV[tid] = 3.402823466e38f;
        sBestI[tid] = 0;
        sZn[tid] = g_znorm[row0 + tid];
    }
    // ordered before any read by the first __syncthreads below

    const float* Ablk = Z + (size_t)row0 * ZD;

    // loader mapping (round-5): thread covers (m0,c40) and (m1,c41), 4 k each
    const int q0 = tid, q1 = tid + 256;
    const int m0 = q0 >> 2, c40 = (q0 & 3) * 4;
    const int m1 = q1 >> 2, c41 = (q1 & 3) * 4;

    for (int ct = 0; ct < KCODES; ct += BN) {
        ull acc[4][8];   // [row-pair][code]; lanes = rows (2i, 2i+1)
#pragma unroll
        for (int i = 0; i < 4; i++)
#pragma unroll
            for (int j = 0; j < 8; j++) acc[i][j] = 0ull;

        const float* Bblk = E + (size_t)ct * ZD;

        // ---- fill buffer 0 with chunk 0 ----
        {
            float4 a0 = *(const float4*)(Ablk + (size_t)m0 * ZD + c40);
            float4 a1 = *(const float4*)(Ablk + (size_t)m1 * ZD + c41);
            float4 b0 = *(const float4*)(Bblk + (size_t)m0 * ZD + c40);
            float4 b1 = *(const float4*)(Bblk + (size_t)m1 * ZD + c41);
            float* Aw = &sA[0][0]; float* Bw = &sB[0][0];
            Aw[(c40 + 0) * LDA + m0] = a0.x; Aw[(c40 + 1) * LDA + m0] = a0.y;
            Aw[(c40 + 2) * LDA + m0] = a0.z; Aw[(c40 + 3) * LDA + m0] = a0.w;
            Aw[(c41 + 0) * LDA + m1] = a1.x; Aw[(c41 + 1) * LDA + m1] = a1.y;
            Aw[(c41 + 2) * LDA + m1] = a1.z; Aw[(c41 + 3) * LDA + m1] = a1.w;
            Bw[(c40 + 0) * LDA + m0] = b0.x; Bw[(c40 + 1) * LDA + m0] = b0.y;
            Bw[(c40 + 2) * LDA + m0] = b0.z; Bw[(c40 + 3) * LDA + m0] = b0.w;
            Bw[(c41 + 0) * LDA + m1] = b1.x; Bw[(c41 + 1) * LDA + m1] = b1.y;
            Bw[(c41 + 2) * LDA + m1] = b1.z; Bw[(c41 + 3) * LDA + m1] = b1.w;
        }

        int buf = 0;
        for (int k0 = 0; k0 < ZD; k0 += BK) {    // k strictly ascending (serial order)
            const int nxt = k0 + BK;
            float4 a0, a1, b0, b1;
            if (nxt < ZD) {                       // prefetch next chunk before the barrier
                a0 = *(const float4*)(Ablk + (size_t)m0 * ZD + nxt + c40);
                a1 = *(const float4*)(Ablk + (size_t)m1 * ZD + nxt + c41);
                b0 = *(const float4*)(Bblk + (size_t)m0 * ZD + nxt + c40);
                b1 = *(const float4*)(Bblk + (size_t)m1 * ZD + nxt + c41);
            }
            __syncthreads();   // prev chunk's compute done -> buf^1 free; buf stores visible
            if (nxt < ZD) {    // fill alternate buffer; overlaps with compute below
                float* Aw = &sA[buf ^ 1][0]; float* Bw = &sB[buf ^ 1][0];
                Aw[(c40 + 0) * LDA + m0] = a0.x; Aw[(c40 + 1) * LDA + m0] = a0.y;
                Aw[(c40 + 2) * LDA + m0] = a0.z; Aw[(c40 + 3) * LDA + m0] = a0.w;
                Aw[(c41 + 0) * LDA + m1] = a1.x; Aw[(c41 + 1) * LDA + m1] = a1.y;
                Aw[(c41 + 2) * LDA + m1] = a1.z; Aw[(c41 + 3) * LDA + m1] = a1.w;
                Bw[(c40 + 0) * LDA + m0] = b0.x; Bw[(c40 + 1) * LDA + m0] = b0.y;
                Bw[(c40 + 2) * LDA + m0] = b0.z; Bw[(c40 + 3) * LDA + m0] = b0.w;
                Bw[(c41 + 0) * LDA + m1] = b1.x; Bw[(c41 + 1) * LDA + m1] = b1.y;
                Bw[(c41 + 2) * LDA + m1] = b1.z; Bw[(c41 + 3) * LDA + m1] = b1.w;
            }
            const float* Ar = &sA[buf][0];
            const float* Br = &sB[buf][0];
#pragma unroll
            for (int kk = 0; kk < BK; kk++) {
                const float* ar = Ar + kk * LDA + ty * 8;
                ulonglong2 t0 = *(const ulonglong2*)(ar);
                ulonglong2 t1 = *(const ulonglong2*)(ar + 4);
                ull a2[4] = { t0.x, t0.y, t1.x, t1.y };
                const float* br = Br + kk * LDA + tx * 8;
                float4 bq0 = *(const float4*)(br);
                float4 bq1 = *(const float4*)(br + 4);
                ull b2[8];
                b2[0] = pack2(bq0.x, bq0.x); b2[1] = pack2(bq0.y, bq0.y);
                b2[2] = pack2(bq0.z, bq0.z); b2[3] = pack2(bq0.w, bq0.w);
                b2[4] = pack2(bq1.x, bq1.x); b2[5] = pack2(bq1.y, bq1.y);
                b2[6] = pack2(bq1.z, bq1.z); b2[7] = pack2(bq1.w, bq1.w);
#pragma unroll
                for (int j = 0; j < 8; j++)
#pragma unroll
                    for (int i = 0; i < 4; i++)
                        acc[i][j] = ffma2(a2[i], b2[j], acc[i][j]);
            }
            buf ^= 1;
        }

        // ---- reference-exact scores: s = fl(fl(zn+en) - 2*dot); argmin, first-index ----
        float v[8]; int vi[8];
#pragma unroll
        for (int r = 0; r < 8; r++) { v[r] = 3.402823466e38f; vi[r] = 0; }
#pragma unroll
        for (int j = 0; j < 8; j++) {
            int c = ct + tx * 8 + j;
            float en = g_enorm[c];
#pragma unroll
            for (int i = 0; i < 4; i++) {
                float lo, hi; unpack2(lo, hi, acc[i][j]);
                float tLo = __fadd_rn(sZn[ty * 8 + 2 * i], en);
                float tHi = __fadd_rn(sZn[ty * 8 + 2 * i + 1], en);
                float sLo = __fmaf_rn(-2.0f, lo, tLo);  // 2*dot exact -> single rounding
                float sHi = __fmaf_rn(-2.0f, hi, tHi);
                if (sLo < v[2 * i])     { v[2 * i] = sLo;     vi[2 * i] = c; }
                if (sHi < v[2 * i + 1]) { v[2 * i + 1] = sHi; vi[2 * i + 1] = c; }
            }
        }
#pragma unroll
        for (int r = 0; r < 8; r++) {
            float mv = v[r]; int mi = vi[r];
#pragma unroll
            for (int o = 8; o; o >>= 1) {
                float ov = __shfl_xor_sync(0xffffffffu, mv, o);
                int   oi = __shfl_xor_sync(0xffffffffu, mi, o);
                if (ov < mv || (ov == mv && oi < mi)) { mv = ov; mi = oi; }
            }
            if (tx == 0) {
                int rr = ty * 8 + r;
                if (mv < sBestV[rr] || (mv == sBestV[rr] && mi < sBestI[rr])) {
                    sBestV[rr] = mv; sBestI[rr] = mi;
                }
            }
        }
    }
    __syncthreads();

    // ---- gather z_q; z_q_st = fl(z + fl(z_q - z)) exactly as reference; loss partial ----
    float lsum = 0.0f;
    for (int e = tid; e < BM * (ZD / 4); e += 256) {
        int m = e >> 6;
        int c4 = (e & 63) * 4;
        int idx = sBestI[m];
        float4 q  = *(const float4*)(E + (size_t)idx * ZD + c4);
        float4 z4 = *(const float4*)(Ablk + (size_t)m * ZD + c4);
        float d0 = __fadd_rn(q.x, -z4.x), d1 = __fadd_rn(q.y, -z4.y);
        float d2 = __fadd_rn(q.z, -z4.z), d3 = __fadd_rn(q.w, -z4.w);
        float4 o;
        o.x = __fadd_rn(z4.x, d0); o.y = __fadd_rn(z4.y, d1);
        o.z = __fadd_rn(z4.z, d2); o.w = __fadd_rn(z4.w, d3);
        lsum += d0 * d0 + d1 * d1 + d2 * d2 + d3 * d3;
        *(float4*)(out + (size_t)(row0 + m) * ZD + c4) = o;
    }
    if (tid < BM) out[IDX_OFF + row0 + tid] = (float)sBestI[tid];

#pragma unroll
    for (int o = 16; o; o >>= 1) lsum += __shfl_xor_sync(0xffffffffu, lsum, o);
    if ((tid & 31) == 0) sRed[tid >> 5] = lsum;
    __syncthreads();
    if (tid < 8) {
        float x = sRed[tid];
        x += __shfl_xor_sync(0xffu, x, 4);
        x += __shfl_xor_sync(0xffu, x, 2);
        x += __shfl_xor_sync(0xffu, x, 1);
        if (tid == 0) g_partial[blockIdx.x] = x;
    }
}

// ================= K3: deterministic final loss reduction =================
__global__ void finalize_kernel(float* __restrict__ out) {
    __shared__ float s[16];
    int t = threadIdx.x;
    float v = g_partial[t];
#pragma unroll
    for (int o = 16; o; o >>= 1) v += __shfl_xor_sync(0xffffffffu, v, o);
    if ((t & 31) == 0) s[t >> 5] = v;
    __syncthreads();
    if (t < 16) {
        float x = s[t];
        x += __shfl_xor_sync(0xffffu, x, 8);
        x += __shfl_xor_sync(0xffffu, x, 4);
        x += __shfl_xor_sync(0xffffu, x, 2);
        x += __shfl_xor_sync(0xffffu, x, 1);
        if (t == 0) {
            float mean = x / (float)((size_t)NROWS * ZD);
            out[LOSS_OFF] = mean + 0.25f * mean;   // (1 + BETA) * mean((z_q - z)^2)
        }
    }
}

extern "C" void kernel_launch(void* const* d_in, const int* in_sizes, int n_in,
                              void* d_out, int out_size) {
    const float* Z = (const float*)d_in[0];
    const float* E = (const float*)d_in[1];
    if (n_in >= 2 && in_sizes[0] < in_sizes[1]) { const float* t = Z; Z = E; E = t; }
    float* out = (float*)d_out;

    sqsum_tree_kernel<<<(NROWS + 7) / 8, 256>>>(Z, NROWS, 0);   // -> g_znorm
    sqsum_tree_kernel<<<(KCODES + 7) / 8, 256>>>(E, KCODES, 1); // -> g_enorm
    vq_main<<<NBLK, 256>>>(Z, E, out);
    finalize_kernel<<<1, 512>>>(out);
}

// round 8
// speedup vs baseline: 3.0928x; 2.3907x over previous
#include <cuda_runtime.h>
#include <cuda_bf16.h>
#include <cuda_fp16.h>

#define NROWS 65536
#define ZD    256
#define KCODES 1024
#define BM 128
#define NBLK (NROWS / BM)    // 512
#define LDT 264              // bf16 smem row stride (256 + 8 pad -> conflict-free frags)
#define MARGIN 8e-3f

#define ZQ_ELEMS ((size_t)NROWS * ZD)
#define IDX_OFF  ZQ_ELEMS
#define LOSS_OFF (ZQ_ELEMS + (size_t)NROWS)

#define SMEM_TILES (2 * BM * LDT * 2)   // 135168 bytes dynamic smem

typedef unsigned long long ull;

__device__ float  g_enorm[KCODES];
__device__ float  g_znorm[NROWS];
__device__ float  g_partial[NBLK];
__device__ __half2 g_srel[(size_t)NROWS * (KCODES / 2)];   // 128 MB scratch: -2*dot as f16

// ================= K1: sum-of-squares per row, XLA row-reduce-tree bit-exact ==========
__global__ void sqsum_tree_kernel(const float* __restrict__ src, int nrows, int mode)
{
    int row = blockIdx.x * 8 + (threadIdx.x >> 5);
    if (row >= nrows) return;
    int lane = threadIdx.x & 31;
    const float2* p = (const float2*)(src + (size_t)row * ZD);

    float acc[4];
#pragma unroll
    for (int j = 0; j < 4; j++) {
        float2 v = p[lane + 32 * j];
        float a = __fmul_rn(v.x, v.x);
        float b = __fmul_rn(v.y, v.y);
        acc[j] = __fadd_rn(a, b);
    }
#pragma unroll
    for (int off = 16; off; off >>= 1) {
#pragma unroll
        for (int j = 0; j < 4; j++)
            acc[j] = __fadd_rn(acc[j], __shfl_down_sync(0xffffffffu, acc[j], off));
    }
    if (lane == 0) {
        float l = __fadd_rn(acc[0], acc[2]);
        float r = __fadd_rn(acc[1], acc[3]);
        float s = __fadd_rn(l, r);
        if (mode == 0) g_znorm[row] = s;
        else           g_enorm[row] = s;
    }
}

// ================= K2: bf16 tensor-core candidate search + exact fp32 rescore ==========
__global__ __launch_bounds__(256, 1) void vq_tensor(
    const float* __restrict__ Z, const float* __restrict__ E, float* __restrict__ out)
{
    extern __shared__ __align__(16) __nv_bfloat16 smem[];
    __nv_bfloat16* sZ = smem;             // [128][LDT]
    __nv_bfloat16* sE = smem + BM * LDT;  // [128][LDT]

    __shared__ float sEn[KCODES];
    __shared__ float sMin[BM];
    __shared__ ull   sBest[BM];
    __shared__ unsigned sCand[8][512];
    __shared__ int   sCnt[8];
    __shared__ float sRed[8];

    const int tid = threadIdx.x;
    const int wid = tid >> 5, lane = tid & 31;
    const int g = lane >> 2, t = lane & 3;      // mma fragment coords
    const int row0 = blockIdx.x * BM;
    const int wr = wid * 16;                     // warp's local row base

    for (int i = tid; i < KCODES; i += 256) sEn[i] = g_enorm[i];
    if (tid < BM) sBest[tid] = ~0ull;
    if (tid < 8)  sCnt[tid] = 0;

    // ---- load + convert Z block to bf16 smem ----
    for (int it = 0; it < 32; it++) {
        int lin = (tid + it * 256) * 4;
        int r = lin >> 8, k = lin & 255;
        float4 v = *(const float4*)(Z + (size_t)(row0 + r) * ZD + k);
        __nv_bfloat162* dst = (__nv_bfloat162*)(sZ + r * LDT + k);
        dst[0] = __floats2bfloat162_rn(v.x, v.y);
        dst[1] = __floats2bfloat162_rn(v.z, v.w);
    }

    float minA = 3.402823466e38f, minB = 3.402823466e38f;

    // ================= phase 1: bf16 mma over all code tiles =================
    for (int ct = 0; ct < 8; ct++) {
        __syncthreads();   // protect sE (and first-iter sZ/sEn) ordering
        for (int it = 0; it < 32; it++) {
            int lin = (tid + it * 256) * 4;
            int r = lin >> 8, k = lin & 255;
            float4 v = *(const float4*)(E + (size_t)(ct * 128 + r) * ZD + k);
            __nv_bfloat162* dst = (__nv_bfloat162*)(sE + r * LDT + k);
            dst[0] = __floats2bfloat162_rn(v.x, v.y);
            dst[1] = __floats2bfloat162_rn(v.z, v.w);
        }
        __syncthreads();

        float dacc[16][4];
#pragma unroll
        for (int nb = 0; nb < 16; nb++) {
            dacc[nb][0] = 0.f; dacc[nb][1] = 0.f; dacc[nb][2] = 0.f; dacc[nb][3] = 0.f;
        }

#pragma unroll 2
        for (int ks = 0; ks < 16; ks++) {
            const __nv_bfloat16* za = sZ + (wr + g) * LDT + ks * 16 + 2 * t;
            unsigned a0 = *(const unsigned*)(za);
            unsigned a1 = *(const unsigned*)(za + 8 * LDT);
            unsigned a2 = *(const unsigned*)(za + 8);
            unsigned a3 = *(const unsigned*)(za + 8 * LDT + 8);
#pragma unroll
            for (int nb = 0; nb < 16; nb++) {
                const __nv_bfloat16* eb = sE + (nb * 8 + g) * LDT + ks * 16 + 2 * t;
                unsigned b0 = *(const unsigned*)(eb);
                unsigned b1 = *(const unsigned*)(eb + 8);
                asm volatile(
                    "mma.sync.aligned.m16n8k16.row.col.f32.bf16.bf16.f32 "
                    "{%0,%1,%2,%3}, {%4,%5,%6,%7}, {%8,%9}, {%0,%1,%2,%3};"
                    : "+f"(dacc[nb][0]), "+f"(dacc[nb][1]),
                      "+f"(dacc[nb][2]), "+f"(dacc[nb][3])
                    : "r"(a0), "r"(a1), "r"(a2), "r"(a3), "r"(b0), "r"(b1));
            }
        }

        // approx vals, running per-row mins, srel store
#pragma unroll
        for (int nb = 0; nb < 16; nb++) {
            int c = ct * 128 + nb * 8 + 2 * t;
            float e0 = sEn[c], e1 = sEn[c + 1];
            float m00 = -2.0f * dacc[nb][0], m01 = -2.0f * dacc[nb][1];
            float m10 = -2.0f * dacc[nb][2], m11 = -2.0f * dacc[nb][3];
            minA = fminf(minA, fminf(e0 + m00, e1 + m01));   // row wr+g
            minB = fminf(minB, fminf(e0 + m10, e1 + m11));   // row wr+g+8
            g_srel[(size_t)(row0 + wr + g) * 512 + (c >> 1)]     = __floats2half2_rn(m00, m01);
            g_srel[(size_t)(row0 + wr + g + 8) * 512 + (c >> 1)] = __floats2half2_rn(m10, m11);
        }
    }

    // per-row approx min: reduce over the 4 t-lanes of each quad
    minA = fminf(minA, __shfl_xor_sync(0xffffffffu, minA, 1));
    minA = fminf(minA, __shfl_xor_sync(0xffffffffu, minA, 2));
    minB = fminf(minB, __shfl_xor_sync(0xffffffffu, minB, 1));
    minB = fminf(minB, __shfl_xor_sync(0xffffffffu, minB, 2));
    if (t == 0) { sMin[wr + g] = minA; sMin[wr + g + 8] = minB; }
    __syncthreads();

    // ================= phase 2: candidate scan (srel rows are L2-hot) =================
    for (int i = 0; i < 16; i++) {
        int rl = wr + i;
        float lim = sMin[rl] + MARGIN;
        const uint4* srow = (const uint4*)(g_srel + (size_t)(row0 + rl) * 512);
#pragma unroll
        for (int ch = 0; ch < 4; ch++) {
            uint4 u = srow[ch * 32 + lane];
            int cb = (ch * 32 + lane) * 8;
            unsigned w[4] = { u.x, u.y, u.z, u.w };
#pragma unroll
            for (int q = 0; q < 4; q++) {
                __half2 h = *reinterpret_cast<__half2*>(&w[q]);
                float2 f = __half22float2(h);
                int c0 = cb + 2 * q;
                if (sEn[c0] + f.x < lim) {
                    int slot = atomicAdd(&sCnt[wid], 1);
                    if (slot < 512) sCand[wid][slot] = (unsigned)((i << 10) | c0);
                }
                if (sEn[c0 + 1] + f.y < lim) {
                    int slot = atomicAdd(&sCnt[wid], 1);
                    if (slot < 512) sCand[wid][slot] = (unsigned)((i << 10) | (c0 + 1));
                }
            }
        }
    }
    __syncwarp();

    // ================= phase 3: exact fp32 rescore (reference op order) =================
    int cnt = sCnt[wid]; if (cnt > 512) cnt = 512;
    for (int base = 0; base < cnt; base += 32) {
        int idx = base + lane;
        if (idx < cnt) {
            unsigned e = sCand[wid][idx];
            int i = e >> 10, c = e & 1023;
            int r = row0 + wr + i;
            const float4* zp = (const float4*)(Z + (size_t)r * ZD);
            const float4* ep = (const float4*)(E + (size_t)c * ZD);
            float acc = 0.0f;            // serial k-ascending single-accumulator chain
#pragma unroll 8
            for (int k = 0; k < 64; k++) {
                float4 a = zp[k]; float4 b = ep[k];
                acc = __fmaf_rn(a.x, b.x, acc);
                acc = __fmaf_rn(a.y, b.y, acc);
                acc = __fmaf_rn(a.z, b.z, acc);
                acc = __fmaf_rn(a.w, b.w, acc);
            }
            float s = __fmaf_rn(-2.0f, acc, __fadd_rn(g_znorm[r], sEn[c]));
            ull key = ((ull)__float_as_uint(s) << 32) | (unsigned)c;  // s > 0 always
            atomicMin(&sBest[wr + i], key);    // min score, tie -> min index
        }
    }
    __syncthreads();

    // ================= epilogue: gather z_q; z_q_st = fl(z + fl(z_q - z)); loss ========
    const float* Ablk = Z + (size_t)row0 * ZD;
    float lsum = 0.0f;
    for (int e2 = tid; e2 < BM * (ZD / 4); e2 += 256) {
        int m = e2 >> 6;
        int c4 = (e2 & 63) * 4;
        int idx = (int)(unsigned)(sBest[m] & 0xffffffffull);
        float4 q  = *(const float4*)(E + (size_t)idx * ZD + c4);
        float4 z4 = *(const float4*)(Ablk + (size_t)m * ZD + c4);
        float d0 = __fadd_rn(q.x, -z4.x), d1 = __fadd_rn(q.y, -z4.y);
        float d2 = __fadd_rn(q.z, -z4.z), d3 = __fadd_rn(q.w, -z4.w);
        float4 o;
        o.x = __fadd_rn(z4.x, d0); o.y = __fadd_rn(z4.y, d1);
        o.z = __fadd_rn(z4.z, d2); o.w = __fadd_rn(z4.w, d3);
        lsum += d0 * d0 + d1 * d1 + d2 * d2 + d3 * d3;
        *(float4*)(out + (size_t)(row0 + m) * ZD + c4) = o;
    }
    if (tid < BM) out[IDX_OFF + row0 + tid] = (float)(unsigned)(sBest[tid] & 0xffffffffull);

#pragma unroll
    for (int o = 16; o; o >>= 1) lsum += __shfl_xor_sync(0xffffffffu, lsum, o);
    if ((tid & 31) == 0) sRed[tid >> 5] = lsum;
    __syncthreads();
    if (tid < 8) {
        float x = sRed[tid];
        x += __shfl_xor_sync(0xffu, x, 4);
        x += __shfl_xor_sync(0xffu, x, 2);
        x += __shfl_xor_sync(0xffu, x, 1);
        if (tid == 0) g_partial[blockIdx.x] = x;
    }
}

// ================= K3: deterministic final loss reduction =================
__global__ void finalize_kernel(float* __restrict__ out) {
    __shared__ float s[16];
    int t = threadIdx.x;
    float v = g_partial[t];
#pragma unroll
    for (int o = 16; o; o >>= 1) v += __shfl_xor_sync(0xffffffffu, v, o);
    if ((t & 31) == 0) s[t >> 5] = v;
    __syncthreads();
    if (t < 16) {
        float x = s[t];
        x += __shfl_xor_sync(0xffffu, x, 8);
        x += __shfl_xor_sync(0xffffu, x, 4);
        x += __shfl_xor_sync(0xffffu, x, 2);
        x += __shfl_xor_sync(0xffffu, x, 1);
        if (t == 0) {
            float mean = x / (float)((size_t)NROWS * ZD);
            out[LOSS_OFF] = mean + 0.25f * mean;   // (1 + BETA) * mean((z_q - z)^2)
        }
    }
}

extern "C" void kernel_launch(void* const* d_in, const int* in_sizes, int n_in,
                              void* d_out, int out_size) {
    const float* Z = (const float*)d_in[0];
    const float* E = (const float*)d_in[1];
    if (n_in >= 2 && in_sizes[0] < in_sizes[1]) { const float* t = Z; Z = E; E = t; }
    float* out = (float*)d_out;

    cudaFuncSetAttribute(vq_tensor, cudaFuncAttributeMaxDynamicSharedMemorySize, SMEM_TILES);

    sqsum_tree_kernel<<<(NROWS + 7) / 8, 256>>>(Z, NROWS, 0);   // -> g_znorm
    sqsum_tree_kernel<<<(KCODES + 7) / 8, 256>>>(E, KCODES, 1); // -> g_enorm
    vq_tensor<<<NBLK, 256, SMEM_TILES>>>(Z, E, out);
    finalize_kernel<<<1, 512>>>(out);
}